// round 15
// baseline (speedup 1.0000x reference)
#include <cuda_runtime.h>
#include <cuda_bf16.h>
#include <cstdint>

#define NN 52
#define NE 832
#define E2 884
#define FD 256
#define NT 256
#define RSX 258   // padded row stride (words)

// W fragments: [w][ks(16)][ntile(32)][lane(32)] = {bh0,bh1,bl0,bl1}
__device__ __align__(16) uint4 g_bf[2*16*32*32];

union F2U { float2 f; unsigned long long u; };
__device__ __forceinline__ unsigned long long pack2(float a, float b){
    F2U t; t.f = make_float2(a, b); return t.u;
}
__device__ __forceinline__ float2 unpack2(unsigned long long v){
    F2U t; t.u = v; return t.f;
}
__device__ __forceinline__ void fma2(unsigned long long& d,
                                     unsigned long long a,
                                     unsigned long long b){
    asm("fma.rn.f32x2 %0, %1, %2, %0;" : "+l"(d) : "l"(a), "l"(b));
}
__device__ __forceinline__ float sigmoidf_(float x){
    return 1.f / (1.f + __expf(-x));
}
// pack two fp32 -> bf16x2 (first arg -> low half)
__device__ __forceinline__ uint32_t bfpack(float lo, float hi){
    uint32_t r;
    asm("cvt.rn.bf16x2.f32 %0, %1, %2;" : "=r"(r) : "f"(hi), "f"(lo));
    return r;
}
__device__ __forceinline__ float bflo(uint32_t p){ return __uint_as_float(p << 16); }
__device__ __forceinline__ float bfhi(uint32_t p){ return __uint_as_float(p & 0xffff0000u); }

__device__ __forceinline__ void mma16816(float* d,
    uint32_t a0, uint32_t a1, uint32_t a2, uint32_t a3,
    uint32_t b0, uint32_t b1){
    asm volatile(
        "mma.sync.aligned.m16n8k16.row.col.f32.bf16.bf16.f32 "
        "{%0,%1,%2,%3},{%4,%5,%6,%7},{%8,%9},{%0,%1,%2,%3};"
        : "+f"(d[0]), "+f"(d[1]), "+f"(d[2]), "+f"(d[3])
        : "r"(a0), "r"(a1), "r"(a2), "r"(a3), "r"(b0), "r"(b1));
}

// ------- W prep: build bf16 hi/lo fragment blocks -------
__global__ void wprep_kernel(const float* __restrict__ W0, const float* __restrict__ W1){
    int i = blockIdx.x * blockDim.x + threadIdx.x;   // 32768
    if (i >= 2*16*32*32) return;
    int lane = i & 31;
    int nt   = (i >> 5) & 31;
    int ks   = (i >> 10) & 15;
    int w    = (i >> 14) & 1;
    int gg = lane >> 2, tg = lane & 3;
    int col = nt*8 + gg;
    int kb  = ks*16;
    const float* W = w ? W1 : W0;
    float f00 = W[(kb + tg*2    )*FD + col];
    float f01 = W[(kb + tg*2 + 1)*FD + col];
    float f10 = W[(kb + 8 + tg*2    )*FD + col];
    float f11 = W[(kb + 8 + tg*2 + 1)*FD + col];
    uint32_t bh0 = bfpack(f00, f01);
    uint32_t bh1 = bfpack(f10, f11);
    uint32_t bl0 = bfpack(f00 - bflo(bh0), f01 - bfhi(bh0));
    uint32_t bl1 = bfpack(f10 - bflo(bh1), f11 - bfhi(bh1));
    g_bf[i] = make_uint4(bh0, bh1, bl0, bl1);
}

// smem: act + xp + alpha + src(442w!) + small + off
constexpr int SRCW = 442;    // 884 shorts
constexpr int SM_WORDS = 2*NN*RSX + E2 + SRCW + 5*NN + (NN+1);
constexpr int SMEM_BYTES = SM_WORDS * 4;

__global__ void __launch_bounds__(NT, 2)
gcab_kernel(const float* __restrict__ xg, const void* __restrict__ eig,
            const float* __restrict__ as0, const float* __restrict__ ad0,
            const float* __restrict__ b0,
            const float* __restrict__ as1, const float* __restrict__ ad1,
            const float* __restrict__ b1,
            const float* __restrict__ Wm, const float* __restrict__ bm,
            const float* __restrict__ wgp, const float* __restrict__ bgp,
            float* __restrict__ outg)
{
    extern __shared__ float sm[];
    float* act   = sm;                      // [52][258]
    float* xp    = act + NN*RSX;            // [52][258]
    float* sAlpha= xp + NN*RSX;             // [884]
    short* sSrc  = (short*)(sAlpha + E2);   // [884] shorts = 442 words
    float* sAsrc = sAlpha + E2 + SRCW;      // [52]
    float* sAdst = sAsrc + NN;              // [52]
    float* sHmax = sAdst + NN;              // [52]
    float* sDinv = sHmax + NN;              // [52]
    float* sMno  = sDinv + NN;              // [52]
    int*   sOff  = (int*)(sMno + NN);       // [53]
    // setup overlays in xp
    int* sS   = (int*)xp;
    int* sD   = sS + E2;
    int* sCnt = sD + E2;
    // epilogue overlays in xp
    float* sAvg = xp;
    float* sMx  = xp + FD;
    float* sMch = xp + 2*FD;
    __shared__ int sIs64;

    const int tid  = threadIdx.x;
    const int g    = blockIdx.x;
    const int lane = tid & 31, wrp = tid >> 5;

    if (tid == 0){
        const int* e32 = (const int*)eig;
        int flag = 1;
        #pragma unroll 1
        for (int i = 0; i < 32; i++){
            if (e32[2*i + 1] != 0){ flag = 0; break; }
        }
        sIs64 = flag;
    }

    // load x row-major
    {
        const float* xr = xg + (size_t)g*NN*FD;
        for (int i = tid; i < NN*FD; i += NT){
            int r = i >> 8, f = i & 255;
            act[r*RSX + f] = xr[i];
        }
        if (tid < NN) sCnt[tid] = 0;
    }
    __syncthreads();

    // edges
    {
        const int is64 = sIs64;
        const long long* ei64 = (const long long*)eig + (size_t)g*2*NE;
        const int*       ei32 = (const int*)eig       + (size_t)g*2*NE;
        for (int e = tid; e < E2; e += NT){
            int s, d;
            if (e < NE){
                if (is64){ s = (int)ei64[e]; d = (int)ei64[NE + e]; }
                else     { s = ei32[e];      d = ei32[NE + e]; }
            } else { s = e - NE; d = e - NE; }
            sS[e] = s; sD[e] = d;
        }
    }
    __syncthreads();
    for (int e = tid; e < E2; e += NT) atomicAdd(&sCnt[sD[e]], 1);
    __syncthreads();
    if (tid == 0){
        int acc = 0;
        for (int i = 0; i < NN; i++){ sOff[i] = acc; acc += sCnt[i]; }
        sOff[NN] = acc;
    }
    if (tid >= 32 && tid < 32 + NN) sDinv[tid-32] = rsqrtf((float)sCnt[tid-32]);
    __syncthreads();
    // deterministic CSR fill: 7 nodes per warp, int16 srcs
    {
        int nds[7], poss[7];
#pragma unroll
        for (int j = 0; j < 7; j++){
            nds[j]  = wrp + 8*j;
            poss[j] = (nds[j] < NN) ? sOff[nds[j]] : 0;
        }
        const unsigned lt = (1u << lane) - 1u;
        for (int base = 0; base < E2; base += 32){
            int e = base + lane;
            int d = -1, s = 0;
            if (e < E2){ d = sD[e]; s = sS[e]; }
#pragma unroll
            for (int j = 0; j < 7; j++){
                unsigned m = __ballot_sync(0xffffffffu, d == nds[j]);
                if (d == nds[j]) sSrc[poss[j] + __popc(m & lt)] = (short)s;
                poss[j] += __popc(m);
            }
        }
    }
    __syncthreads();

    // mma warp mapping
    const int g8 = lane >> 2, tg = lane & 3;
    const int mt = wrp >> 1;      // m-tile 0..3 (rows mt*16..+15)
    const int ng = wrp & 1;       // n-half: cols ng*128..+127 (16 ntiles)
    const float* ar0 = act + (mt*16 + g8)*RSX + tg*2;
    const float* ar1 = ar0 + 8*RSX;

    for (int rnd = 0; rnd < 2; rnd++){
        const float* av = rnd ? as1 : as0;
        const float* dv = rnd ? ad1 : ad0;
        const float* bb = rnd ? b1  : b0;
        __syncthreads();   // xp overlay reuse barrier

        // ---- GEMM: xp[52][256] = act @ W via mma.sync bf16 3-term ----
        {
            float d[16][4];
#pragma unroll
            for (int n = 0; n < 16; n++)
#pragma unroll
                for (int c = 0; c < 4; c++) d[n][c] = 0.f;

            const uint4* bbase = g_bf + ((size_t)rnd << 14) + (ng*16)*32 + lane;
            uint4 bnx = bbase[0];

#pragma unroll 1
            for (int ks = 0; ks < 16; ks++){
                const int kb = ks*16;
                float2 v0 = *(const float2*)(ar0 + kb);
                float2 v1 = *(const float2*)(ar1 + kb);
                float2 v2 = *(const float2*)(ar0 + kb + 8);
                float2 v3 = *(const float2*)(ar1 + kb + 8);
                uint32_t ah0 = bfpack(v0.x, v0.y);
                uint32_t ah1 = bfpack(v1.x, v1.y);
                uint32_t ah2 = bfpack(v2.x, v2.y);
                uint32_t ah3 = bfpack(v3.x, v3.y);
                uint32_t al0 = bfpack(v0.x - bflo(ah0), v0.y - bfhi(ah0));
                uint32_t al1 = bfpack(v1.x - bflo(ah1), v1.y - bfhi(ah1));
                uint32_t al2 = bfpack(v2.x - bflo(ah2), v2.y - bfhi(ah2));
                uint32_t al3 = bfpack(v3.x - bflo(ah3), v3.y - bfhi(ah3));
#pragma unroll
                for (int nt = 0; nt < 16; nt++){
                    uint4 b = bnx;
                    int nid = ks*16 + nt + 1;
                    if (nid < 256)
                        bnx = bbase[(nid >> 4)*1024 + (nid & 15)*32];
                    mma16816(d[nt], ah0, ah1, ah2, ah3, b.x, b.y);  // Ah*Wh
                    mma16816(d[nt], ah0, ah1, ah2, ah3, b.z, b.w);  // Ah*Wl
                    mma16816(d[nt], al0, al1, al2, al3, b.x, b.y);  // Al*Wh
                }
            }
            // store D -> xp (rows < 52 only)
            int r0 = mt*16 + g8, r1 = r0 + 8;
#pragma unroll
            for (int nt = 0; nt < 16; nt++){
                int col = ng*128 + nt*8 + tg*2;
                if (r0 < NN)
                    *(float2*)(xp + r0*RSX + col) = make_float2(d[nt][0], d[nt][1]);
                if (r1 < NN)
                    *(float2*)(xp + r1*RSX + col) = make_float2(d[nt][2], d[nt][3]);
            }
        }
        __syncthreads();

        // ---- asrc/adst per row (warp-per-row, a_s/a_d loaded from gmem) ----
        {
            F2U avr[4], dvr[4];
#pragma unroll
            for (int t = 0; t < 4; t++){
                avr[t].f = ((const float2*)av)[lane + 32*t];
                dvr[t].f = ((const float2*)dv)[lane + 32*t];
            }
            for (int r = wrp; r < NN; r += 8){
                const float2* vb = (const float2*)(xp + r*RSX);
                unsigned long long sa2 = 0ull, sd2 = 0ull;
#pragma unroll
                for (int t = 0; t < 4; t++){
                    F2U v; v.f = vb[lane + 32*t];
                    fma2(sa2, v.u, avr[t].u);
                    fma2(sd2, v.u, dvr[t].u);
                }
                float2 sap = unpack2(sa2), sdp = unpack2(sd2);
                float sa = sap.x + sap.y, sd = sdp.x + sdp.y;
#pragma unroll
                for (int o = 16; o; o >>= 1){
                    sa += __shfl_down_sync(0xffffffffu, sa, o);
                    sd += __shfl_down_sync(0xffffffffu, sd, o);
                }
                if (lane == 0){ sAsrc[r] = sa; sAdst[r] = sd; }
            }
        }
        __syncthreads();

        // ---- fused logits + softmax (warp per node) ----
        for (int nd = wrp; nd < NN; nd += 8){
            int beg = sOff[nd], end = sOff[nd+1];
            float adn = sAdst[nd];
            float m = -3.0e38f;
            for (int t = beg + lane; t < end; t += 32){
                int src = sSrc[t];
                float el = sAsrc[src] + adn;
                el = el > 0.f ? el : 0.2f * el;
                sAlpha[t] = el;
                m = fmaxf(m, el);
            }
#pragma unroll
            for (int o = 16; o; o >>= 1)
                m = fmaxf(m, __shfl_xor_sync(0xffffffffu, m, o));
            float s = 0.f;
            for (int t = beg + lane; t < end; t += 32){
                float w = __expf(sAlpha[t] - m);
                sAlpha[t] = w;
                s += w;
            }
#pragma unroll
            for (int o = 16; o; o >>= 1)
                s += __shfl_xor_sync(0xffffffffu, s, o);
            float inv = 1.f / s;
            for (int t = beg + lane; t < end; t += 32)
                sAlpha[t] *= inv;
        }
        __syncthreads();

        // ---- aggregation: 128 col-pairs x 2 row halves, pairwise edges ----
        {
            const int p = tid & 127;
            const int q = tid >> 7;
            float2 bbv = ((const float2*)bb)[p];
            for (int dd = q*26; dd < q*26 + 26; dd++){
                int beg = sOff[dd], end = sOff[dd+1];
                unsigned long long acc = 0ull;
                int t = beg;
                if (t & 1){
                    int src = sSrc[t];
                    float al = sAlpha[t];
                    F2U xv; xv.f = ((const float2*)(xp + src*RSX))[p];
                    fma2(acc, xv.u, pack2(al, al));
                    t++;
                }
#pragma unroll 2
                for (; t + 1 < end; t += 2){
                    int spair = *(const int*)&sSrc[t];
                    int s0 = spair & 0xffff, s1 = (spair >> 16) & 0xffff;
                    float2 al2 = *(const float2*)&sAlpha[t];
                    F2U x0; x0.f = ((const float2*)(xp + s0*RSX))[p];
                    F2U x1; x1.f = ((const float2*)(xp + s1*RSX))[p];
                    fma2(acc, x0.u, pack2(al2.x, al2.x));
                    fma2(acc, x1.u, pack2(al2.y, al2.y));
                }
                if (t < end){
                    int src = sSrc[t];
                    float al = sAlpha[t];
                    F2U xv; xv.f = ((const float2*)(xp + src*RSX))[p];
                    fma2(acc, xv.u, pack2(al, al));
                }
                float2 r = unpack2(acc);
                float v0 = r.x + bbv.x;
                float v1 = r.y + bbv.y;
                float* a0 = act + dd*RSX + 2*p;
                if (rnd == 1){
                    v0 = fmaxf(v0 + a0[0], 0.f);
                    v1 = fmaxf(v1 + a0[1], 0.f);
                }
                a0[0] = v0;
                a0[1] = v1;
            }
        }
        __syncthreads();
    }

    // ---- channel attention (thread = column) ----
    {
        const int j = tid;
        float s = 0.f, m = -3.0e38f;
#pragma unroll 4
        for (int r = 0; r < NN; r++){
            float v = act[r*RSX + j];
            s += v; m = fmaxf(m, v);
        }
        sAvg[j] = s * (1.f/52.f);
        sMx[j]  = m;
    }
    __syncthreads();
    {
        const int j = tid;
        float aA = 0.f, aM = 0.f;
        const float* wc = Wm + j;
#pragma unroll 4
        for (int k = 0; k < FD; k++){
            float w = wc[k*FD];
            aA += sAvg[k]*w;
            aM += sMx[k]*w;
        }
        float bj = bm[j];
        float mval = sigmoidf_(fmaxf(aA + bj, 0.f) + fmaxf(aM + bj, 0.f));
        __syncthreads();
        sMch[j] = mval;
    }
    __syncthreads();

    // ---- node attention ----
    for (int r = wrp; r < NN; r += 8){
        float mx = -3.0e38f;
#pragma unroll
        for (int t = 0; t < 8; t++){
            int f = lane + 32*t;
            mx = fmaxf(mx, act[r*RSX + f] * sMch[f]);
        }
#pragma unroll
        for (int o = 16; o; o >>= 1)
            mx = fmaxf(mx, __shfl_down_sync(0xffffffffu, mx, o));
        if (lane == 0) sHmax[r] = mx;
    }
    __syncthreads();
    if (tid < NN){
        float s = 0.f;
        int beg = sOff[tid], end = sOff[tid+1];
        for (int t = beg; t < end; t++){
            int ss = sSrc[t];
            s += sDinv[ss] * sHmax[ss];
        }
        float aggv = sDinv[tid] * s * wgp[0] + bgp[0];
        sMno[tid] = sigmoidf_(aggv);
    }
    __syncthreads();

    // ---- final write ----
    {
        const int j = tid;
        float mch = sMch[j];
        float* op = outg + (size_t)g*NN*FD + j;
#pragma unroll 4
        for (int r = 0; r < NN; r++)
            op[r*FD] = act[r*RSX + j] * mch * sMno[r];
    }
}

extern "C" void kernel_launch(void* const* d_in, const int* in_sizes, int n_in,
                              void* d_out, int out_size)
{
    const float* x   = (const float*)d_in[0];
    const void*  ei  = d_in[1];
    const float* W0  = (const float*)d_in[2];
    const float* as0 = (const float*)d_in[3];
    const float* ad0 = (const float*)d_in[4];
    const float* b0  = (const float*)d_in[5];
    const float* W1  = (const float*)d_in[6];
    const float* as1 = (const float*)d_in[7];
    const float* ad1 = (const float*)d_in[8];
    const float* b1  = (const float*)d_in[9];
    const float* Wm  = (const float*)d_in[10];
    const float* bm  = (const float*)d_in[11];
    const float* wg  = (const float*)d_in[12];
    const float* bg  = (const float*)d_in[13];
    float* out = (float*)d_out;

    int B = in_sizes[0] / (NN*FD);

    wprep_kernel<<<128, 256>>>(W0, W1);
    cudaFuncSetAttribute(gcab_kernel,
                         cudaFuncAttributeMaxDynamicSharedMemorySize,
                         SMEM_BYTES);
    gcab_kernel<<<B, NT, SMEM_BYTES>>>(x, ei, as0, ad0, b0,
                                       as1, ad1, b1, Wm, bm, wg, bg, out);
}

// round 16
// speedup vs baseline: 1.6586x; 1.6586x over previous
#include <cuda_runtime.h>
#include <cuda_bf16.h>
#include <cstdint>

#define NN 52
#define NE 832
#define E2 884
#define FD 256
#define NT 256
#define RSX 258   // padded row stride (words)

// W fragments: [w][ks(16)][ntile(32)][lane(32)] = {bh0,bh1,bl0,bl1}
__device__ __align__(16) uint4 g_bf[2*16*32*32];

union F2U { float2 f; unsigned long long u; };
__device__ __forceinline__ unsigned long long pack2(float a, float b){
    F2U t; t.f = make_float2(a, b); return t.u;
}
__device__ __forceinline__ float2 unpack2(unsigned long long v){
    F2U t; t.u = v; return t.f;
}
__device__ __forceinline__ void fma2(unsigned long long& d,
                                     unsigned long long a,
                                     unsigned long long b){
    asm("fma.rn.f32x2 %0, %1, %2, %0;" : "+l"(d) : "l"(a), "l"(b));
}
__device__ __forceinline__ float sigmoidf_(float x){
    return 1.f / (1.f + __expf(-x));
}
// pack two fp32 -> bf16x2 (first arg -> low half)
__device__ __forceinline__ uint32_t bfpack(float lo, float hi){
    uint32_t r;
    asm("cvt.rn.bf16x2.f32 %0, %1, %2;" : "=r"(r) : "f"(hi), "f"(lo));
    return r;
}
__device__ __forceinline__ float bflo(uint32_t p){ return __uint_as_float(p << 16); }
__device__ __forceinline__ float bfhi(uint32_t p){ return __uint_as_float(p & 0xffff0000u); }

__device__ __forceinline__ void mma16816(float* d,
    uint32_t a0, uint32_t a1, uint32_t a2, uint32_t a3,
    uint32_t b0, uint32_t b1){
    asm volatile(
        "mma.sync.aligned.m16n8k16.row.col.f32.bf16.bf16.f32 "
        "{%0,%1,%2,%3},{%4,%5,%6,%7},{%8,%9},{%0,%1,%2,%3};"
        : "+f"(d[0]), "+f"(d[1]), "+f"(d[2]), "+f"(d[3])
        : "r"(a0), "r"(a1), "r"(a2), "r"(a3), "r"(b0), "r"(b1));
}

// ------- W prep: build bf16 hi/lo fragment blocks -------
__global__ void wprep_kernel(const float* __restrict__ W0, const float* __restrict__ W1){
    int i = blockIdx.x * blockDim.x + threadIdx.x;   // 32768
    if (i >= 2*16*32*32) return;
    int lane = i & 31;
    int nt   = (i >> 5) & 31;
    int ks   = (i >> 10) & 15;
    int w    = (i >> 14) & 1;
    int gg = lane >> 2, tg = lane & 3;
    int col = nt*8 + gg;
    int kb  = ks*16;
    const float* W = w ? W1 : W0;
    float f00 = W[(kb + tg*2    )*FD + col];
    float f01 = W[(kb + tg*2 + 1)*FD + col];
    float f10 = W[(kb + 8 + tg*2    )*FD + col];
    float f11 = W[(kb + 8 + tg*2 + 1)*FD + col];
    uint32_t bh0 = bfpack(f00, f01);
    uint32_t bh1 = bfpack(f10, f11);
    uint32_t bl0 = bfpack(f00 - bflo(bh0), f01 - bfhi(bh0));
    uint32_t bl1 = bfpack(f10 - bflo(bh1), f11 - bfhi(bh1));
    g_bf[i] = make_uint4(bh0, bh1, bl0, bl1);
}

constexpr int SRCW = 442;    // 884 shorts
constexpr int SM_WORDS = 2*NN*RSX + E2 + SRCW + 5*NN + (NN+1);
constexpr int SMEM_BYTES = SM_WORDS * 4;

__global__ void __launch_bounds__(NT, 2)
gcab_kernel(const float* __restrict__ xg, const void* __restrict__ eig,
            const float* __restrict__ as0, const float* __restrict__ ad0,
            const float* __restrict__ b0,
            const float* __restrict__ as1, const float* __restrict__ ad1,
            const float* __restrict__ b1,
            const float* __restrict__ Wm, const float* __restrict__ bm,
            const float* __restrict__ wgp, const float* __restrict__ bgp,
            float* __restrict__ outg)
{
    extern __shared__ float sm[];
    float* act   = sm;                      // [52][258]
    float* xp    = act + NN*RSX;            // [52][258]
    float* sAlpha= xp + NN*RSX;             // [884]
    short* sSrc  = (short*)(sAlpha + E2);   // [884] shorts = 442 words
    float* sAsrc = sAlpha + E2 + SRCW;      // [52]
    float* sAdst = sAsrc + NN;              // [52]
    float* sHmax = sAdst + NN;              // [52]
    float* sDinv = sHmax + NN;              // [52]
    float* sMno  = sDinv + NN;              // [52]
    int*   sOff  = (int*)(sMno + NN);       // [53]
    // setup overlays in xp
    int* sS   = (int*)xp;
    int* sD   = sS + E2;
    int* sCnt = sD + E2;
    // epilogue overlays in xp
    float* sAvg = xp;
    float* sMx  = xp + FD;
    float* sMch = xp + 2*FD;
    __shared__ int sIs64;

    const int tid  = threadIdx.x;
    const int g    = blockIdx.x;
    const int lane = tid & 31, wrp = tid >> 5;

    if (tid == 0){
        const int* e32 = (const int*)eig;
        int flag = 1;
        #pragma unroll 1
        for (int i = 0; i < 32; i++){
            if (e32[2*i + 1] != 0){ flag = 0; break; }
        }
        sIs64 = flag;
    }

    // load x row-major
    {
        const float* xr = xg + (size_t)g*NN*FD;
        for (int i = tid; i < NN*FD; i += NT){
            int r = i >> 8, f = i & 255;
            act[r*RSX + f] = xr[i];
        }
        if (tid < NN) sCnt[tid] = 0;
    }
    __syncthreads();

    // edges
    {
        const int is64 = sIs64;
        const long long* ei64 = (const long long*)eig + (size_t)g*2*NE;
        const int*       ei32 = (const int*)eig       + (size_t)g*2*NE;
        for (int e = tid; e < E2; e += NT){
            int s, d;
            if (e < NE){
                if (is64){ s = (int)ei64[e]; d = (int)ei64[NE + e]; }
                else     { s = ei32[e];      d = ei32[NE + e]; }
            } else { s = e - NE; d = e - NE; }
            sS[e] = s; sD[e] = d;
        }
    }
    __syncthreads();
    for (int e = tid; e < E2; e += NT) atomicAdd(&sCnt[sD[e]], 1);
    __syncthreads();
    if (tid == 0){
        int acc = 0;
        for (int i = 0; i < NN; i++){ sOff[i] = acc; acc += sCnt[i]; }
        sOff[NN] = acc;
    }
    if (tid >= 32 && tid < 32 + NN) sDinv[tid-32] = rsqrtf((float)sCnt[tid-32]);
    __syncthreads();
    // deterministic CSR fill: 7 nodes per warp, int16 srcs
    {
        int nds[7], poss[7];
#pragma unroll
        for (int j = 0; j < 7; j++){
            nds[j]  = wrp + 8*j;
            poss[j] = (nds[j] < NN) ? sOff[nds[j]] : 0;
        }
        const unsigned lt = (1u << lane) - 1u;
        for (int base = 0; base < E2; base += 32){
            int e = base + lane;
            int d = -1, s = 0;
            if (e < E2){ d = sD[e]; s = sS[e]; }
#pragma unroll
            for (int j = 0; j < 7; j++){
                unsigned m = __ballot_sync(0xffffffffu, d == nds[j]);
                if (d == nds[j]) sSrc[poss[j] + __popc(m & lt)] = (short)s;
                poss[j] += __popc(m);
            }
        }
    }
    __syncthreads();

    // mma warp mapping
    const int g8 = lane >> 2, tg = lane & 3;
    const int mt = wrp >> 1;      // m-tile 0..3 (rows mt*16..+15)
    const int ng = wrp & 1;       // n-half (16 ntiles), split into 2 passes of 8
    const float* ar0 = act + (mt*16 + g8)*RSX + tg*2;
    const float* ar1 = ar0 + 8*RSX;

    for (int rnd = 0; rnd < 2; rnd++){
        const float* av = rnd ? as1 : as0;
        const float* dv = rnd ? ad1 : ad0;
        const float* bb = rnd ? b1  : b0;
        __syncthreads();   // xp overlay reuse barrier

        // ---- GEMM: xp[52][256] = act @ W via mma.sync bf16 3-term ----
        // 2 passes x 8 ntiles; rolling 8-deep B prefetch (MLP=8)
#pragma unroll 1
        for (int p = 0; p < 2; p++){
            float d[8][4];
#pragma unroll
            for (int n = 0; n < 8; n++)
#pragma unroll
                for (int c = 0; c < 4; c++) d[n][c] = 0.f;

            // base of this pass's 8 ntiles at ks=0
            const uint4* bb2 = g_bf + (((size_t)rnd*16)*32 + ng*16 + p*8)*32 + lane;
            uint4 buf[8];
#pragma unroll
            for (int j = 0; j < 8; j++) buf[j] = bb2[j*32];

#pragma unroll 1
            for (int ks = 0; ks < 16; ks++){
                const int kb = ks*16;
                float2 v0 = *(const float2*)(ar0 + kb);
                float2 v1 = *(const float2*)(ar1 + kb);
                float2 v2 = *(const float2*)(ar0 + kb + 8);
                float2 v3 = *(const float2*)(ar1 + kb + 8);
                uint32_t ah0 = bfpack(v0.x, v0.y);
                uint32_t ah1 = bfpack(v1.x, v1.y);
                uint32_t ah2 = bfpack(v2.x, v2.y);
                uint32_t ah3 = bfpack(v3.x, v3.y);
                uint32_t al0 = bfpack(v0.x - bflo(ah0), v0.y - bfhi(ah0));
                uint32_t al1 = bfpack(v1.x - bflo(ah1), v1.y - bfhi(ah1));
                uint32_t al2 = bfpack(v2.x - bflo(ah2), v2.y - bfhi(ah2));
                uint32_t al3 = bfpack(v3.x - bflo(ah3), v3.y - bfhi(ah3));
                // next-ks fragment block (clamped at the end; redundant reload)
                const uint4* nb = bb2 + (size_t)((ks < 15) ? ks + 1 : ks)*1024;
#pragma unroll
                for (int nt = 0; nt < 8; nt++){
                    uint4 b = buf[nt];
                    buf[nt] = nb[nt*32];          // rolling prefetch, distance 8
                    mma16816(d[nt], ah0, ah1, ah2, ah3, b.x, b.y);  // Ah*Wh
                    mma16816(d[nt], ah0, ah1, ah2, ah3, b.z, b.w);  // Ah*Wl
                    mma16816(d[nt], al0, al1, al2, al3, b.x, b.y);  // Al*Wh
                }
            }
            // store D -> xp (rows < 52 only)
            int r0 = mt*16 + g8, r1 = r0 + 8;
#pragma unroll
            for (int nt = 0; nt < 8; nt++){
                int col = ng*128 + p*64 + nt*8 + tg*2;
                if (r0 < NN)
                    *(float2*)(xp + r0*RSX + col) = make_float2(d[nt][0], d[nt][1]);
                if (r1 < NN)
                    *(float2*)(xp + r1*RSX + col) = make_float2(d[nt][2], d[nt][3]);
            }
        }
        __syncthreads();

        // ---- asrc/adst per row (warp-per-row, a_s/a_d loaded from gmem) ----
        {
            F2U avr[4], dvr[4];
#pragma unroll
            for (int t = 0; t < 4; t++){
                avr[t].f = ((const float2*)av)[lane + 32*t];
                dvr[t].f = ((const float2*)dv)[lane + 32*t];
            }
            for (int r = wrp; r < NN; r += 8){
                const float2* vb = (const float2*)(xp + r*RSX);
                unsigned long long sa2 = 0ull, sd2 = 0ull;
#pragma unroll
                for (int t = 0; t < 4; t++){
                    F2U v; v.f = vb[lane + 32*t];
                    fma2(sa2, v.u, avr[t].u);
                    fma2(sd2, v.u, dvr[t].u);
                }
                float2 sap = unpack2(sa2), sdp = unpack2(sd2);
                float sa = sap.x + sap.y, sd = sdp.x + sdp.y;
#pragma unroll
                for (int o = 16; o; o >>= 1){
                    sa += __shfl_down_sync(0xffffffffu, sa, o);
                    sd += __shfl_down_sync(0xffffffffu, sd, o);
                }
                if (lane == 0){ sAsrc[r] = sa; sAdst[r] = sd; }
            }
        }
        __syncthreads();

        // ---- fused logits + softmax (warp per node) ----
        for (int nd = wrp; nd < NN; nd += 8){
            int beg = sOff[nd], end = sOff[nd+1];
            float adn = sAdst[nd];
            float m = -3.0e38f;
            for (int t = beg + lane; t < end; t += 32){
                int src = sSrc[t];
                float el = sAsrc[src] + adn;
                el = el > 0.f ? el : 0.2f * el;
                sAlpha[t] = el;
                m = fmaxf(m, el);
            }
#pragma unroll
            for (int o = 16; o; o >>= 1)
                m = fmaxf(m, __shfl_xor_sync(0xffffffffu, m, o));
            float s = 0.f;
            for (int t = beg + lane; t < end; t += 32){
                float w = __expf(sAlpha[t] - m);
                sAlpha[t] = w;
                s += w;
            }
#pragma unroll
            for (int o = 16; o; o >>= 1)
                s += __shfl_xor_sync(0xffffffffu, s, o);
            float inv = 1.f / s;
            for (int t = beg + lane; t < end; t += 32)
                sAlpha[t] *= inv;
        }
        __syncthreads();

        // ---- aggregation: 128 col-pairs x 2 row halves, pairwise edges ----
        {
            const int p = tid & 127;
            const int q = tid >> 7;
            float2 bbv = ((const float2*)bb)[p];
            for (int dd = q*26; dd < q*26 + 26; dd++){
                int beg = sOff[dd], end = sOff[dd+1];
                unsigned long long acc = 0ull;
                int t = beg;
                if (t & 1){
                    int src = sSrc[t];
                    float al = sAlpha[t];
                    F2U xv; xv.f = ((const float2*)(xp + src*RSX))[p];
                    fma2(acc, xv.u, pack2(al, al));
                    t++;
                }
#pragma unroll 2
                for (; t + 1 < end; t += 2){
                    int spair = *(const int*)&sSrc[t];
                    int s0 = spair & 0xffff, s1 = (spair >> 16) & 0xffff;
                    float2 al2 = *(const float2*)&sAlpha[t];
                    F2U x0; x0.f = ((const float2*)(xp + s0*RSX))[p];
                    F2U x1; x1.f = ((const float2*)(xp + s1*RSX))[p];
                    fma2(acc, x0.u, pack2(al2.x, al2.x));
                    fma2(acc, x1.u, pack2(al2.y, al2.y));
                }
                if (t < end){
                    int src = sSrc[t];
                    float al = sAlpha[t];
                    F2U xv; xv.f = ((const float2*)(xp + src*RSX))[p];
                    fma2(acc, xv.u, pack2(al, al));
                }
                float2 r = unpack2(acc);
                float v0 = r.x + bbv.x;
                float v1 = r.y + bbv.y;
                float* a0 = act + dd*RSX + 2*p;
                if (rnd == 1){
                    v0 = fmaxf(v0 + a0[0], 0.f);
                    v1 = fmaxf(v1 + a0[1], 0.f);
                }
                a0[0] = v0;
                a0[1] = v1;
            }
        }
        __syncthreads();
    }

    // ---- channel attention (thread = column) ----
    {
        const int j = tid;
        float s = 0.f, m = -3.0e38f;
#pragma unroll 4
        for (int r = 0; r < NN; r++){
            float v = act[r*RSX + j];
            s += v; m = fmaxf(m, v);
        }
        sAvg[j] = s * (1.f/52.f);
        sMx[j]  = m;
    }
    __syncthreads();
    {
        const int j = tid;
        float aA = 0.f, aM = 0.f;
        const float* wc = Wm + j;
#pragma unroll 4
        for (int k = 0; k < FD; k++){
            float w = wc[k*FD];
            aA += sAvg[k]*w;
            aM += sMx[k]*w;
        }
        float bj = bm[j];
        float mval = sigmoidf_(fmaxf(aA + bj, 0.f) + fmaxf(aM + bj, 0.f));
        __syncthreads();
        sMch[j] = mval;
    }
    __syncthreads();

    // ---- node attention ----
    for (int r = wrp; r < NN; r += 8){
        float mx = -3.0e38f;
#pragma unroll
        for (int t = 0; t < 8; t++){
            int f = lane + 32*t;
            mx = fmaxf(mx, act[r*RSX + f] * sMch[f]);
        }
#pragma unroll
        for (int o = 16; o; o >>= 1)
            mx = fmaxf(mx, __shfl_down_sync(0xffffffffu, mx, o));
        if (lane == 0) sHmax[r] = mx;
    }
    __syncthreads();
    if (tid < NN){
        float s = 0.f;
        int beg = sOff[tid], end = sOff[tid+1];
        for (int t = beg; t < end; t++){
            int ss = sSrc[t];
            s += sDinv[ss] * sHmax[ss];
        }
        float aggv = sDinv[tid] * s * wgp[0] + bgp[0];
        sMno[tid] = sigmoidf_(aggv);
    }
    __syncthreads();

    // ---- final write ----
    {
        const int j = tid;
        float mch = sMch[j];
        float* op = outg + (size_t)g*NN*FD + j;
#pragma unroll 4
        for (int r = 0; r < NN; r++)
            op[r*FD] = act[r*RSX + j] * mch * sMno[r];
    }
}

extern "C" void kernel_launch(void* const* d_in, const int* in_sizes, int n_in,
                              void* d_out, int out_size)
{
    const float* x   = (const float*)d_in[0];
    const void*  ei  = d_in[1];
    const float* W0  = (const float*)d_in[2];
    const float* as0 = (const float*)d_in[3];
    const float* ad0 = (const float*)d_in[4];
    const float* b0  = (const float*)d_in[5];
    const float* W1  = (const float*)d_in[6];
    const float* as1 = (const float*)d_in[7];
    const float* ad1 = (const float*)d_in[8];
    const float* b1  = (const float*)d_in[9];
    const float* Wm  = (const float*)d_in[10];
    const float* bm  = (const float*)d_in[11];
    const float* wg  = (const float*)d_in[12];
    const float* bg  = (const float*)d_in[13];
    float* out = (float*)d_out;

    int B = in_sizes[0] / (NN*FD);

    wprep_kernel<<<128, 256>>>(W0, W1);
    cudaFuncSetAttribute(gcab_kernel,
                         cudaFuncAttributeMaxDynamicSharedMemorySize,
                         SMEM_BYTES);
    gcab_kernel<<<B, NT, SMEM_BYTES>>>(x, ei, as0, ad0, b0,
                                       as1, ad1, b1, Wm, bm, wg, bg, out);
}